// round 6
// baseline (speedup 1.0000x reference)
#include <cuda_runtime.h>

#define NU 100000
#define NI 50000
#define NE 1600000
#define D  128

// ---------------- scratch (device globals) ----------------------------------
__device__ int g_h_fs[NU];
__device__ int g_h_fd[NU];
__device__ int g_h_rs[NU];
__device__ int g_h_rd[NI];
__device__ int g_h_vs[NI];
__device__ int g_h_vd[NU];

__device__ float g_inv_fs[NU];
__device__ float g_inv_fd[NU];
__device__ float g_inv_rs[NU];
__device__ float g_inv_rd[NI];
__device__ float g_inv_vs[NI];
__device__ float g_inv_vd[NU];

__device__ int   g_off_f[NU + 1];
__device__ int   g_off_r[NI + 1];
__device__ int   g_off_v[NU + 1];
__device__ int   g_pos_f[NU];
__device__ int   g_pos_r[NI];
__device__ int   g_pos_v[NU];
__device__ int2  g_ef[NE];   // packed {src, w_bits} sorted by dst
__device__ int2  g_er[NE];
__device__ int2  g_ev[NE];
__device__ int   g_bsum[3][1024];

__device__ float g_hu1[(size_t)NU * D];   // layer-1 transformed feats
__device__ float g_hu2[(size_t)NU * D];
__device__ float g_hi [(size_t)NI * D];
__device__ float g_hu1b[(size_t)NU * D];  // layer-2 transformed feats
__device__ float g_hu2b[(size_t)NU * D];
__device__ float g_hib [(size_t)NI * D];
__device__ float g_u  [(size_t)NU * D];
__device__ float g_it [(size_t)NI * D];

// ---------------- setup kernels ----------------------------------------------

__global__ void k_zero_hists() {
    int i = blockIdx.x * blockDim.x + threadIdx.x;
    if (i < NU) { g_h_fs[i] = 0; g_h_fd[i] = 0; g_h_rs[i] = 0; g_h_vd[i] = 0; }
    if (i < NI) { g_h_rd[i] = 0; g_h_vs[i] = 0; }
}

__global__ void k_hist3(const int* __restrict__ fs, const int* __restrict__ fd,
                        const int* __restrict__ rs, const int* __restrict__ rd,
                        const int* __restrict__ vs, const int* __restrict__ vd) {
    int e = blockIdx.x * blockDim.x + threadIdx.x;
    if (e >= NE) return;
    if (blockIdx.y == 0) {
        atomicAdd(&g_h_fs[fs[e]], 1);
        atomicAdd(&g_h_fd[fd[e]], 1);
    } else if (blockIdx.y == 1) {
        atomicAdd(&g_h_rs[rs[e]], 1);
        atomicAdd(&g_h_rd[rd[e]], 1);
    } else {
        atomicAdd(&g_h_vs[vs[e]], 1);
        atomicAdd(&g_h_vd[vd[e]], 1);
    }
}

__device__ __forceinline__ float invsq(int x) {
    return x > 0 ? rsqrtf((float)x) : 0.f;
}

__global__ void k_inv_all() {
    int i = blockIdx.x * blockDim.x + threadIdx.x;
    if (i < NU) {
        g_inv_fs[i] = invsq(g_h_fs[i]);
        g_inv_fd[i] = invsq(g_h_fd[i]);
        g_inv_rs[i] = invsq(g_h_rs[i]);
        g_inv_vd[i] = invsq(g_h_vd[i]);
    }
    if (i < NI) {
        g_inv_rd[i] = invsq(g_h_rd[i]);
        g_inv_vs[i] = invsq(g_h_vs[i]);
    }
}

// ---------------- exclusive scan (3 arrays per launch via blockIdx.y) ---------

__global__ void k_scan1() {
    __shared__ int s[1024];
    const int* in; int* outp; int n;
    if (blockIdx.y == 0)      { in = g_h_fd; outp = g_off_f; n = NU; }
    else if (blockIdx.y == 1) { in = g_h_rd; outp = g_off_r; n = NI; }
    else                      { in = g_h_vd; outp = g_off_v; n = NU; }
    int tid = threadIdx.x;
    int i = blockIdx.x * 1024 + tid;
    int v = (i < n) ? in[i] : 0;
    s[tid] = v;
    __syncthreads();
#pragma unroll
    for (int o = 1; o < 1024; o <<= 1) {
        int t = (tid >= o) ? s[tid - o] : 0;
        __syncthreads();
        s[tid] += t;
        __syncthreads();
    }
    if (i < n) outp[i] = s[tid] - v;
    if (tid == 1023) g_bsum[blockIdx.y][blockIdx.x] = s[1023];
}

__global__ void k_scan2() {
    __shared__ int s[1024];
    int nb = (blockIdx.x == 1) ? (NI + 1023) / 1024 : (NU + 1023) / 1024;
    int tid = threadIdx.x;
    int v = (tid < nb) ? g_bsum[blockIdx.x][tid] : 0;
    s[tid] = v;
    __syncthreads();
#pragma unroll
    for (int o = 1; o < 1024; o <<= 1) {
        int t = (tid >= o) ? s[tid - o] : 0;
        __syncthreads();
        s[tid] += t;
        __syncthreads();
    }
    if (tid < nb) g_bsum[blockIdx.x][tid] = s[tid] - v;
}

__global__ void k_scan3() {
    int* outp; int* pos; int n;
    if (blockIdx.y == 0)      { outp = g_off_f; pos = g_pos_f; n = NU; }
    else if (blockIdx.y == 1) { outp = g_off_r; pos = g_pos_r; n = NI; }
    else                      { outp = g_off_v; pos = g_pos_v; n = NU; }
    int i = blockIdx.x * blockDim.x + threadIdx.x;
    if (i < n) {
        int v = outp[i] + g_bsum[blockIdx.y][i >> 10];
        outp[i] = v;
        pos[i] = v;
    } else if (i == n) {
        outp[n] = NE;
    }
}

__global__ void k_fill3(const int* __restrict__ fs, const int* __restrict__ fd,
                        const int* __restrict__ rs, const int* __restrict__ rd,
                        const int* __restrict__ vs, const int* __restrict__ vd) {
    int e = blockIdx.x * blockDim.x + threadIdx.x;
    if (e >= NE) return;
    const int *src, *dst; const float* invs;
    int* pos; int2* eout;
    if (blockIdx.y == 0) {
        src = fs; dst = fd; invs = g_inv_fs; pos = g_pos_f; eout = g_ef;
    } else if (blockIdx.y == 1) {
        src = rs; dst = rd; invs = g_inv_rs; pos = g_pos_r; eout = g_er;
    } else {
        src = vs; dst = vd; invs = g_inv_vs; pos = g_pos_v; eout = g_ev;
    }
    int d = dst[e];
    int s = src[e];
    int p = atomicAdd(&pos[d], 1);
    eout[p] = make_int2(s, __float_as_int(invs[s]));
}

// ---------------- GEMM: C[n,128] = A[n,128] @ W[128,128] ----------------------

#define GEMM_SMEM ((128 * 128 + 128 * 64) * 4)  // W 64KB + At 32KB

__global__ void __launch_bounds__(256) k_gemm(const float* __restrict__ A,
                                              const float* __restrict__ W,
                                              float* __restrict__ C, int n) {
    extern __shared__ float sm[];
    float* Ws = sm;               // [128][128]
    float* At = sm + 128 * 128;   // [128 k][64 row]

    for (int i = threadIdx.x; i < 128 * 32; i += 256)
        ((float4*)Ws)[i] = ((const float4*)W)[i];

    int row0 = blockIdx.x * 64;
    for (int i = threadIdx.x; i < 64 * 32; i += 256) {
        int c = i >> 6;
        int r = i & 63;
        int row = row0 + r;
        float4 v = (row < n) ? ((const float4*)A)[(size_t)row * 32 + c]
                             : make_float4(0.f, 0.f, 0.f, 0.f);
        At[(4 * c + 0) * 64 + r] = v.x;
        At[(4 * c + 1) * 64 + r] = v.y;
        At[(4 * c + 2) * 64 + r] = v.z;
        At[(4 * c + 3) * 64 + r] = v.w;
    }
    __syncthreads();

    int ty = threadIdx.x >> 5;
    int tx = threadIdx.x & 31;

    unsigned long long acc[8][2];
#pragma unroll
    for (int r = 0; r < 8; r++) { acc[r][0] = 0ull; acc[r][1] = 0ull; }

    const float* at = At + ty * 8;
#pragma unroll 8
    for (int k = 0; k < 128; k++) {
        ulonglong2 w = ((const ulonglong2*)(Ws + k * 128))[tx];
        float4 a03 = *(const float4*)(at + k * 64);
        float4 a47 = *(const float4*)(at + k * 64 + 4);
        unsigned long long p0, p1, p2, p3, p4, p5, p6, p7;
        asm("mov.b64 %0, {%1, %1};" : "=l"(p0) : "f"(a03.x));
        asm("mov.b64 %0, {%1, %1};" : "=l"(p1) : "f"(a03.y));
        asm("mov.b64 %0, {%1, %1};" : "=l"(p2) : "f"(a03.z));
        asm("mov.b64 %0, {%1, %1};" : "=l"(p3) : "f"(a03.w));
        asm("mov.b64 %0, {%1, %1};" : "=l"(p4) : "f"(a47.x));
        asm("mov.b64 %0, {%1, %1};" : "=l"(p5) : "f"(a47.y));
        asm("mov.b64 %0, {%1, %1};" : "=l"(p6) : "f"(a47.z));
        asm("mov.b64 %0, {%1, %1};" : "=l"(p7) : "f"(a47.w));
        asm("fma.rn.f32x2 %0, %1, %2, %0;" : "+l"(acc[0][0]) : "l"(p0), "l"(w.x));
        asm("fma.rn.f32x2 %0, %1, %2, %0;" : "+l"(acc[0][1]) : "l"(p0), "l"(w.y));
        asm("fma.rn.f32x2 %0, %1, %2, %0;" : "+l"(acc[1][0]) : "l"(p1), "l"(w.x));
        asm("fma.rn.f32x2 %0, %1, %2, %0;" : "+l"(acc[1][1]) : "l"(p1), "l"(w.y));
        asm("fma.rn.f32x2 %0, %1, %2, %0;" : "+l"(acc[2][0]) : "l"(p2), "l"(w.x));
        asm("fma.rn.f32x2 %0, %1, %2, %0;" : "+l"(acc[2][1]) : "l"(p2), "l"(w.y));
        asm("fma.rn.f32x2 %0, %1, %2, %0;" : "+l"(acc[3][0]) : "l"(p3), "l"(w.x));
        asm("fma.rn.f32x2 %0, %1, %2, %0;" : "+l"(acc[3][1]) : "l"(p3), "l"(w.y));
        asm("fma.rn.f32x2 %0, %1, %2, %0;" : "+l"(acc[4][0]) : "l"(p4), "l"(w.x));
        asm("fma.rn.f32x2 %0, %1, %2, %0;" : "+l"(acc[4][1]) : "l"(p4), "l"(w.y));
        asm("fma.rn.f32x2 %0, %1, %2, %0;" : "+l"(acc[5][0]) : "l"(p5), "l"(w.x));
        asm("fma.rn.f32x2 %0, %1, %2, %0;" : "+l"(acc[5][1]) : "l"(p5), "l"(w.y));
        asm("fma.rn.f32x2 %0, %1, %2, %0;" : "+l"(acc[6][0]) : "l"(p6), "l"(w.x));
        asm("fma.rn.f32x2 %0, %1, %2, %0;" : "+l"(acc[6][1]) : "l"(p6), "l"(w.y));
        asm("fma.rn.f32x2 %0, %1, %2, %0;" : "+l"(acc[7][0]) : "l"(p7), "l"(w.x));
        asm("fma.rn.f32x2 %0, %1, %2, %0;" : "+l"(acc[7][1]) : "l"(p7), "l"(w.y));
    }

#pragma unroll
    for (int r = 0; r < 8; r++) {
        int row = row0 + ty * 8 + r;
        if (row < n) {
            float4 o;
            asm("mov.b64 {%0, %1}, %2;" : "=f"(o.x), "=f"(o.y) : "l"(acc[r][0]));
            asm("mov.b64 {%0, %1}, %2;" : "=f"(o.z), "=f"(o.w) : "l"(acc[r][1]));
            ((float4*)C)[(size_t)row * 32 + tx] = o;
        }
    }
}

// ---------------- CSR gather-aggregate (2-wide, packed edges) ------------------

__device__ __forceinline__ float4 agg_list(const float* __restrict__ h,
                                           const int2* __restrict__ eds,
                                           int j, int end, int lane) {
    float x = 0.f, y = 0.f, z = 0.f, w = 0.f;
    if (j < end && (j & 1)) {
        int2 e = __ldg(eds + j);
        float w0 = __int_as_float(e.y);
        float4 v0 = __ldg((const float4*)(h + (size_t)e.x * D) + lane);
        x += w0 * v0.x; y += w0 * v0.y; z += w0 * v0.z; w += w0 * v0.w;
        j++;
    }
    for (; j + 1 < end; j += 2) {
        int4 ee = __ldg((const int4*)(eds + j));
        float w0 = __int_as_float(ee.y);
        float w1 = __int_as_float(ee.w);
        float4 v0 = __ldg((const float4*)(h + (size_t)ee.x * D) + lane);
        float4 v1 = __ldg((const float4*)(h + (size_t)ee.z * D) + lane);
        x += w0 * v0.x + w1 * v1.x;
        y += w0 * v0.y + w1 * v1.y;
        z += w0 * v0.z + w1 * v1.z;
        w += w0 * v0.w + w1 * v1.w;
    }
    if (j < end) {
        int2 e = __ldg(eds + j);
        float w0 = __int_as_float(e.y);
        float4 v0 = __ldg((const float4*)(h + (size_t)e.x * D) + lane);
        x += w0 * v0.x; y += w0 * v0.y; z += w0 * v0.z; w += w0 * v0.w;
    }
    return make_float4(x, y, z, w);
}

template <bool RELU>
__global__ void __launch_bounds__(256) k_agg_user(
    const float* __restrict__ hF, const float* __restrict__ hV,
    const float* __restrict__ bF, const float* __restrict__ bV,
    float* __restrict__ outp) {
    int warp = (blockIdx.x * blockDim.x + threadIdx.x) >> 5;
    if (warp >= NU) return;
    int lane = threadIdx.x & 31;

    float4 aF = agg_list(hF, g_ef, g_off_f[warp], g_off_f[warp + 1], lane);
    float4 aV = agg_list(hV, g_ev, g_off_v[warp], g_off_v[warp + 1], lane);
    float fF = g_inv_fd[warp];
    float fV = g_inv_vd[warp];
    float4 b1 = __ldg((const float4*)bF + lane);
    float4 b2 = __ldg((const float4*)bV + lane);

    float4 o;
    o.x = 0.5f * (fF * aF.x + fV * aV.x + b1.x + b2.x);
    o.y = 0.5f * (fF * aF.y + fV * aV.y + b1.y + b2.y);
    o.z = 0.5f * (fF * aF.z + fV * aV.z + b1.z + b2.z);
    o.w = 0.5f * (fF * aF.w + fV * aV.w + b1.w + b2.w);
    if (RELU) {
        o.x = fmaxf(o.x, 0.f); o.y = fmaxf(o.y, 0.f);
        o.z = fmaxf(o.z, 0.f); o.w = fmaxf(o.w, 0.f);
    }
    ((float4*)outp)[(size_t)warp * 32 + lane] = o;
}

template <bool RELU>
__global__ void __launch_bounds__(256) k_agg_item(
    const float* __restrict__ h, const float* __restrict__ b,
    float* __restrict__ outp) {
    int warp = (blockIdx.x * blockDim.x + threadIdx.x) >> 5;
    if (warp >= NI) return;
    int lane = threadIdx.x & 31;

    float4 a = agg_list(h, g_er, g_off_r[warp], g_off_r[warp + 1], lane);
    float f = g_inv_rd[warp];
    float4 bb = __ldg((const float4*)b + lane);

    float4 o;
    o.x = f * a.x + bb.x;
    o.y = f * a.y + bb.y;
    o.z = f * a.z + bb.z;
    o.w = f * a.w + bb.w;
    if (RELU) {
        o.x = fmaxf(o.x, 0.f); o.y = fmaxf(o.y, 0.f);
        o.z = fmaxf(o.z, 0.f); o.w = fmaxf(o.w, 0.f);
    }
    ((float4*)outp)[(size_t)warp * 32 + lane] = o;
}

// ---------------- host driver --------------------------------------------------

extern "C" void kernel_launch(void* const* d_in, const int* in_sizes, int n_in,
                              void* d_out, int out_size) {
    const float* x_user = (const float*)d_in[0];
    const float* x_item = (const float*)d_in[1];
    const int* f_src = (const int*)d_in[2];
    const int* f_dst = (const int*)d_in[3];
    const int* r_src = (const int*)d_in[4];
    const int* r_dst = (const int*)d_in[5];
    const int* v_src = (const int*)d_in[6];
    const int* v_dst = (const int*)d_in[7];

    const float *W1f, *W1r, *W1v, *W2f, *W2r, *W2v;
    const float *b1f, *b1r, *b1v, *b2f, *b2r, *b2v;
    if (in_sizes[9] == 128 * 128) {
        W1f = (const float*)d_in[8];  W1r = (const float*)d_in[9];  W1v = (const float*)d_in[10];
        W2f = (const float*)d_in[11]; W2r = (const float*)d_in[12]; W2v = (const float*)d_in[13];
        b1f = (const float*)d_in[14]; b1r = (const float*)d_in[15]; b1v = (const float*)d_in[16];
        b2f = (const float*)d_in[17]; b2r = (const float*)d_in[18]; b2v = (const float*)d_in[19];
    } else {
        W1f = (const float*)d_in[8];  b1f = (const float*)d_in[9];
        W1r = (const float*)d_in[10]; b1r = (const float*)d_in[11];
        W1v = (const float*)d_in[12]; b1v = (const float*)d_in[13];
        W2f = (const float*)d_in[14]; b2f = (const float*)d_in[15];
        W2r = (const float*)d_in[16]; b2r = (const float*)d_in[17];
        W2v = (const float*)d_in[18]; b2v = (const float*)d_in[19];
    }
    float* out = (float*)d_out;

    float *hu1, *hu2, *hi, *hu1b, *hu2b, *hib, *u, *it;
    cudaGetSymbolAddress((void**)&hu1, g_hu1);
    cudaGetSymbolAddress((void**)&hu2, g_hu2);
    cudaGetSymbolAddress((void**)&hi,  g_hi);
    cudaGetSymbolAddress((void**)&hu1b, g_hu1b);
    cudaGetSymbolAddress((void**)&hu2b, g_hu2b);
    cudaGetSymbolAddress((void**)&hib,  g_hib);
    cudaGetSymbolAddress((void**)&u,  g_u);
    cudaGetSymbolAddress((void**)&it, g_it);

    static cudaStream_t s1 = 0;
    static cudaEvent_t evFork = 0, evCSR = 0, evU = 0, evW2f = 0, evW2r = 0,
                       evItG = 0, evEnd = 0;
    if (s1 == 0) {
        cudaStreamCreateWithFlags(&s1, cudaStreamNonBlocking);
        cudaEventCreateWithFlags(&evFork, cudaEventDisableTiming);
        cudaEventCreateWithFlags(&evCSR,  cudaEventDisableTiming);
        cudaEventCreateWithFlags(&evU,    cudaEventDisableTiming);
        cudaEventCreateWithFlags(&evW2f,  cudaEventDisableTiming);
        cudaEventCreateWithFlags(&evW2r,  cudaEventDisableTiming);
        cudaEventCreateWithFlags(&evItG,  cudaEventDisableTiming);
        cudaEventCreateWithFlags(&evEnd,  cudaEventDisableTiming);
    }

    const int TB = 256;
    cudaFuncSetAttribute(k_gemm, cudaFuncAttributeMaxDynamicSharedMemorySize, GEMM_SMEM);

    int gNU   = (NU + TB - 1) / TB;
    int gAggU = (NU * 32 + TB - 1) / TB;
    int gAggI = (NI * 32 + TB - 1) / TB;
    int nbU = (NU + 1023) / 1024;

    dim3 gEdge3((NE + TB - 1) / TB, 3);
    dim3 gScan1(nbU, 3);
    dim3 gScan3((NU + 1 + TB - 1) / TB, 3);

    // ---- s1: CSR build, then the entire item pipeline ------------------------
    cudaEventRecord(evFork, 0);
    cudaStreamWaitEvent(s1, evFork, 0);
    k_zero_hists<<<gNU, TB, 0, s1>>>();
    k_hist3<<<gEdge3, TB, 0, s1>>>(f_src, f_dst, r_src, r_dst, v_src, v_dst);
    k_inv_all<<<gNU, TB, 0, s1>>>();
    k_scan1<<<gScan1, 1024, 0, s1>>>();
    k_scan2<<<3, 1024, 0, s1>>>();
    k_scan3<<<gScan3, TB, 0, s1>>>();
    k_fill3<<<gEdge3, TB, 0, s1>>>(f_src, f_dst, r_src, r_dst, v_src, v_dst);
    cudaEventRecord(evCSR, s1);

    // item pipeline stays on s1 (CSR already ordered before it):
    // hu2 GEMM (overlaps user agg1 on s0), agg_item1, it@W2v
    k_gemm<<<(NU + 63) / 64, 256, GEMM_SMEM, s1>>>(x_user, W1r, hu2, NU);
    k_agg_item<true><<<gAggI, TB, 0, s1>>>(hu2, b1r, it);
    k_gemm<<<(NI + 63) / 64, 256, GEMM_SMEM, s1>>>(it, W2v, hib, NI);
    cudaEventRecord(evItG, s1);

    // ---- s0: user-critical path ----------------------------------------------
    k_gemm<<<(NU + 63) / 64, 256, GEMM_SMEM>>>(x_user, W1f, hu1, NU);
    k_gemm<<<(NI + 63) / 64, 256, GEMM_SMEM>>>(x_item, W1v, hi,  NI);
    cudaStreamWaitEvent(0, evCSR, 0);
    k_agg_user<true><<<gAggU, TB>>>(hu1, hi, b1f, b1v, u);
    cudaEventRecord(evU, 0);
    k_gemm<<<(NU + 63) / 64, 256, GEMM_SMEM>>>(u, W2f, hu1b, NU);
    cudaEventRecord(evW2f, 0);

    // W2r moves to s1-side ordering: launch on s1 after u is ready, so s0 can
    // proceed straight into agg_user2 once hib lands.
    cudaStreamWaitEvent(s1, evU, 0);
    k_gemm<<<(NU + 63) / 64, 256, GEMM_SMEM, s1>>>(u, W2r, hu2b, NU);
    k_agg_item<false><<<gAggI, TB, 0, s1>>>(hu2b, b2r, out + (size_t)NU * D);
    cudaEventRecord(evEnd, s1);

    // final user agg on s0: needs hu1b (evW2f, in-order) + hib (evItG)
    cudaStreamWaitEvent(0, evItG, 0);
    k_agg_user<false><<<gAggU, TB>>>(hu1b, hib, b2f, b2v, out);
    cudaStreamWaitEvent(0, evEnd, 0);  // join
}

// round 8
// speedup vs baseline: 1.1248x; 1.1248x over previous
#include <cuda_runtime.h>
#include <cuda_fp16.h>

#define NU 100000
#define NI 50000
#define NE 1600000
#define D  128

// ---------------- scratch (device globals) ----------------------------------
__device__ int g_h_fs[NU];
__device__ int g_h_fd[NU];
__device__ int g_h_rs[NU];
__device__ int g_h_rd[NI];
__device__ int g_h_vs[NI];
__device__ int g_h_vd[NU];

__device__ float g_inv_fs[NU];
__device__ float g_inv_fd[NU];
__device__ float g_inv_rs[NU];
__device__ float g_inv_rd[NI];
__device__ float g_inv_vs[NI];
__device__ float g_inv_vd[NU];

__device__ int   g_off_f[NU + 1];
__device__ int   g_off_r[NI + 1];
__device__ int   g_off_v[NU + 1];
__device__ int   g_pos_f[NU];
__device__ int   g_pos_r[NI];
__device__ int   g_pos_v[NU];
__device__ int2  g_ef[NE];   // packed {src, w_bits} sorted by dst
__device__ int2  g_er[NE];
__device__ int2  g_ev[NE];
__device__ int   g_bsum[3][1024];

// h buffers in fp16 (gather hot path); u/it in fp32 (GEMM inputs)
__device__ __half g_hu1[(size_t)NU * D];
__device__ __half g_hu2[(size_t)NU * D];
__device__ __half g_hi [(size_t)NI * D];
__device__ __half g_hu1b[(size_t)NU * D];
__device__ __half g_hu2b[(size_t)NU * D];
__device__ __half g_hib [(size_t)NI * D];
__device__ float  g_u  [(size_t)NU * D];
__device__ float  g_it [(size_t)NI * D];

// ---------------- setup kernels ----------------------------------------------

__global__ void k_zero_hists() {
    int i = blockIdx.x * blockDim.x + threadIdx.x;
    if (i < NU) { g_h_fs[i] = 0; g_h_fd[i] = 0; g_h_rs[i] = 0; g_h_vd[i] = 0; }
    if (i < NI) { g_h_rd[i] = 0; g_h_vs[i] = 0; }
}

__global__ void k_hist3(const int* __restrict__ fs, const int* __restrict__ fd,
                        const int* __restrict__ rs, const int* __restrict__ rd,
                        const int* __restrict__ vs, const int* __restrict__ vd) {
    int e = blockIdx.x * blockDim.x + threadIdx.x;
    if (e >= NE) return;
    if (blockIdx.y == 0) {
        atomicAdd(&g_h_fs[fs[e]], 1);
        atomicAdd(&g_h_fd[fd[e]], 1);
    } else if (blockIdx.y == 1) {
        atomicAdd(&g_h_rs[rs[e]], 1);
        atomicAdd(&g_h_rd[rd[e]], 1);
    } else {
        atomicAdd(&g_h_vs[vs[e]], 1);
        atomicAdd(&g_h_vd[vd[e]], 1);
    }
}

__device__ __forceinline__ float invsq(int x) {
    return x > 0 ? rsqrtf((float)x) : 0.f;
}

__global__ void k_inv_all() {
    int i = blockIdx.x * blockDim.x + threadIdx.x;
    if (i < NU) {
        g_inv_fs[i] = invsq(g_h_fs[i]);
        g_inv_fd[i] = invsq(g_h_fd[i]);
        g_inv_rs[i] = invsq(g_h_rs[i]);
        g_inv_vd[i] = invsq(g_h_vd[i]);
    }
    if (i < NI) {
        g_inv_rd[i] = invsq(g_h_rd[i]);
        g_inv_vs[i] = invsq(g_h_vs[i]);
    }
}

// ---------------- exclusive scan (3 arrays per launch via blockIdx.y) ---------

__global__ void k_scan1() {
    __shared__ int s[1024];
    const int* in; int* outp; int n;
    if (blockIdx.y == 0)      { in = g_h_fd; outp = g_off_f; n = NU; }
    else if (blockIdx.y == 1) { in = g_h_rd; outp = g_off_r; n = NI; }
    else                      { in = g_h_vd; outp = g_off_v; n = NU; }
    int tid = threadIdx.x;
    int i = blockIdx.x * 1024 + tid;
    int v = (i < n) ? in[i] : 0;
    s[tid] = v;
    __syncthreads();
#pragma unroll
    for (int o = 1; o < 1024; o <<= 1) {
        int t = (tid >= o) ? s[tid - o] : 0;
        __syncthreads();
        s[tid] += t;
        __syncthreads();
    }
    if (i < n) outp[i] = s[tid] - v;
    if (tid == 1023) g_bsum[blockIdx.y][blockIdx.x] = s[1023];
}

__global__ void k_scan2() {
    __shared__ int s[1024];
    int nb = (blockIdx.x == 1) ? (NI + 1023) / 1024 : (NU + 1023) / 1024;
    int tid = threadIdx.x;
    int v = (tid < nb) ? g_bsum[blockIdx.x][tid] : 0;
    s[tid] = v;
    __syncthreads();
#pragma unroll
    for (int o = 1; o < 1024; o <<= 1) {
        int t = (tid >= o) ? s[tid - o] : 0;
        __syncthreads();
        s[tid] += t;
        __syncthreads();
    }
    if (tid < nb) g_bsum[blockIdx.x][tid] = s[tid] - v;
}

__global__ void k_scan3() {
    int* outp; int* pos; int n;
    if (blockIdx.y == 0)      { outp = g_off_f; pos = g_pos_f; n = NU; }
    else if (blockIdx.y == 1) { outp = g_off_r; pos = g_pos_r; n = NI; }
    else                      { outp = g_off_v; pos = g_pos_v; n = NU; }
    int i = blockIdx.x * blockDim.x + threadIdx.x;
    if (i < n) {
        int v = outp[i] + g_bsum[blockIdx.y][i >> 10];
        outp[i] = v;
        pos[i] = v;
    } else if (i == n) {
        outp[n] = NE;
    }
}

__global__ void k_fill3(const int* __restrict__ fs, const int* __restrict__ fd,
                        const int* __restrict__ rs, const int* __restrict__ rd,
                        const int* __restrict__ vs, const int* __restrict__ vd) {
    int e = blockIdx.x * blockDim.x + threadIdx.x;
    if (e >= NE) return;
    const int *src, *dst; const float* invs;
    int* pos; int2* eout;
    if (blockIdx.y == 0) {
        src = fs; dst = fd; invs = g_inv_fs; pos = g_pos_f; eout = g_ef;
    } else if (blockIdx.y == 1) {
        src = rs; dst = rd; invs = g_inv_rs; pos = g_pos_r; eout = g_er;
    } else {
        src = vs; dst = vd; invs = g_inv_vs; pos = g_pos_v; eout = g_ev;
    }
    int d = dst[e];
    int s = src[e];
    int p = atomicAdd(&pos[d], 1);
    eout[p] = make_int2(s, __float_as_int(invs[s]));
}

// ---------------- GEMM: C[n,128](fp16) = A[n,128](fp32) @ W[128,128](fp32) ----
// 64 rows/block, 256 threads, 96KB smem (2 blocks/SM). A staged TRANSPOSED.

#define GEMM_SMEM ((128 * 128 + 128 * 64) * 4)  // W 64KB + At 32KB

__global__ void __launch_bounds__(256) k_gemm(const float* __restrict__ A,
                                              const float* __restrict__ W,
                                              __half* __restrict__ C, int n) {
    extern __shared__ float sm[];
    float* Ws = sm;               // [128][128]
    float* At = sm + 128 * 128;   // [128 k][64 row]

    for (int i = threadIdx.x; i < 128 * 32; i += 256)
        ((float4*)Ws)[i] = ((const float4*)W)[i];

    int row0 = blockIdx.x * 64;
    for (int i = threadIdx.x; i < 64 * 32; i += 256) {
        int c = i >> 6;
        int r = i & 63;
        int row = row0 + r;
        float4 v = (row < n) ? ((const float4*)A)[(size_t)row * 32 + c]
                             : make_float4(0.f, 0.f, 0.f, 0.f);
        At[(4 * c + 0) * 64 + r] = v.x;
        At[(4 * c + 1) * 64 + r] = v.y;
        At[(4 * c + 2) * 64 + r] = v.z;
        At[(4 * c + 3) * 64 + r] = v.w;
    }
    __syncthreads();

    int ty = threadIdx.x >> 5;
    int tx = threadIdx.x & 31;

    unsigned long long acc[8][2];
#pragma unroll
    for (int r = 0; r < 8; r++) { acc[r][0] = 0ull; acc[r][1] = 0ull; }

    const float* at = At + ty * 8;
#pragma unroll 8
    for (int k = 0; k < 128; k++) {
        ulonglong2 w = ((const ulonglong2*)(Ws + k * 128))[tx];
        float4 a03 = *(const float4*)(at + k * 64);
        float4 a47 = *(const float4*)(at + k * 64 + 4);
        unsigned long long p0, p1, p2, p3, p4, p5, p6, p7;
        asm("mov.b64 %0, {%1, %1};" : "=l"(p0) : "f"(a03.x));
        asm("mov.b64 %0, {%1, %1};" : "=l"(p1) : "f"(a03.y));
        asm("mov.b64 %0, {%1, %1};" : "=l"(p2) : "f"(a03.z));
        asm("mov.b64 %0, {%1, %1};" : "=l"(p3) : "f"(a03.w));
        asm("mov.b64 %0, {%1, %1};" : "=l"(p4) : "f"(a47.x));
        asm("mov.b64 %0, {%1, %1};" : "=l"(p5) : "f"(a47.y));
        asm("mov.b64 %0, {%1, %1};" : "=l"(p6) : "f"(a47.z));
        asm("mov.b64 %0, {%1, %1};" : "=l"(p7) : "f"(a47.w));
        asm("fma.rn.f32x2 %0, %1, %2, %0;" : "+l"(acc[0][0]) : "l"(p0), "l"(w.x));
        asm("fma.rn.f32x2 %0, %1, %2, %0;" : "+l"(acc[0][1]) : "l"(p0), "l"(w.y));
        asm("fma.rn.f32x2 %0, %1, %2, %0;" : "+l"(acc[1][0]) : "l"(p1), "l"(w.x));
        asm("fma.rn.f32x2 %0, %1, %2, %0;" : "+l"(acc[1][1]) : "l"(p1), "l"(w.y));
        asm("fma.rn.f32x2 %0, %1, %2, %0;" : "+l"(acc[2][0]) : "l"(p2), "l"(w.x));
        asm("fma.rn.f32x2 %0, %1, %2, %0;" : "+l"(acc[2][1]) : "l"(p2), "l"(w.y));
        asm("fma.rn.f32x2 %0, %1, %2, %0;" : "+l"(acc[3][0]) : "l"(p3), "l"(w.x));
        asm("fma.rn.f32x2 %0, %1, %2, %0;" : "+l"(acc[3][1]) : "l"(p3), "l"(w.y));
        asm("fma.rn.f32x2 %0, %1, %2, %0;" : "+l"(acc[4][0]) : "l"(p4), "l"(w.x));
        asm("fma.rn.f32x2 %0, %1, %2, %0;" : "+l"(acc[4][1]) : "l"(p4), "l"(w.y));
        asm("fma.rn.f32x2 %0, %1, %2, %0;" : "+l"(acc[5][0]) : "l"(p5), "l"(w.x));
        asm("fma.rn.f32x2 %0, %1, %2, %0;" : "+l"(acc[5][1]) : "l"(p5), "l"(w.y));
        asm("fma.rn.f32x2 %0, %1, %2, %0;" : "+l"(acc[6][0]) : "l"(p6), "l"(w.x));
        asm("fma.rn.f32x2 %0, %1, %2, %0;" : "+l"(acc[6][1]) : "l"(p6), "l"(w.y));
        asm("fma.rn.f32x2 %0, %1, %2, %0;" : "+l"(acc[7][0]) : "l"(p7), "l"(w.x));
        asm("fma.rn.f32x2 %0, %1, %2, %0;" : "+l"(acc[7][1]) : "l"(p7), "l"(w.y));
    }

#pragma unroll
    for (int r = 0; r < 8; r++) {
        int row = row0 + ty * 8 + r;
        if (row < n) {
            float4 o;
            asm("mov.b64 {%0, %1}, %2;" : "=f"(o.x), "=f"(o.y) : "l"(acc[r][0]));
            asm("mov.b64 {%0, %1}, %2;" : "=f"(o.z), "=f"(o.w) : "l"(acc[r][1]));
            __half2 h0 = __floats2half2_rn(o.x, o.y);
            __half2 h1 = __floats2half2_rn(o.z, o.w);
            uint2 pk = make_uint2(*(unsigned*)&h0, *(unsigned*)&h1);
            *(uint2*)(C + (size_t)row * D + tx * 4) = pk;
        }
    }
}

// ---------------- CSR gather-aggregate (fp16 gathers, fp32 accum) --------------

__device__ __forceinline__ float4 agg_list(const __half* __restrict__ h,
                                           const int2* __restrict__ eds,
                                           int j, int end, int lane) {
    float x = 0.f, y = 0.f, z = 0.f, w = 0.f;
    if (j < end && (j & 1)) {
        int2 e = __ldg(eds + j);
        float w0 = __int_as_float(e.y);
        uint2 v = __ldg((const uint2*)(h + (size_t)e.x * D) + lane);
        float2 f0 = __half22float2(*(__half2*)&v.x);
        float2 f1 = __half22float2(*(__half2*)&v.y);
        x += w0 * f0.x; y += w0 * f0.y; z += w0 * f1.x; w += w0 * f1.y;
        j++;
    }
    for (; j + 1 < end; j += 2) {
        int4 ee = __ldg((const int4*)(eds + j));
        float w0 = __int_as_float(ee.y);
        float w1 = __int_as_float(ee.w);
        uint2 v0 = __ldg((const uint2*)(h + (size_t)ee.x * D) + lane);
        uint2 v1 = __ldg((const uint2*)(h + (size_t)ee.z * D) + lane);
        float2 a0 = __half22float2(*(__half2*)&v0.x);
        float2 a1 = __half22float2(*(__half2*)&v0.y);
        float2 b0 = __half22float2(*(__half2*)&v1.x);
        float2 b1 = __half22float2(*(__half2*)&v1.y);
        x += w0 * a0.x + w1 * b0.x;
        y += w0 * a0.y + w1 * b0.y;
        z += w0 * a1.x + w1 * b1.x;
        w += w0 * a1.y + w1 * b1.y;
    }
    if (j < end) {
        int2 e = __ldg(eds + j);
        float w0 = __int_as_float(e.y);
        uint2 v = __ldg((const uint2*)(h + (size_t)e.x * D) + lane);
        float2 f0 = __half22float2(*(__half2*)&v.x);
        float2 f1 = __half22float2(*(__half2*)&v.y);
        x += w0 * f0.x; y += w0 * f0.y; z += w0 * f1.x; w += w0 * f1.y;
    }
    return make_float4(x, y, z, w);
}

template <bool RELU>
__global__ void __launch_bounds__(256) k_agg_user(
    const __half* __restrict__ hF, const __half* __restrict__ hV,
    const float* __restrict__ bF, const float* __restrict__ bV,
    float* __restrict__ outp) {
    int warp = (blockIdx.x * blockDim.x + threadIdx.x) >> 5;
    if (warp >= NU) return;
    int lane = threadIdx.x & 31;

    float4 aF = agg_list(hF, g_ef, g_off_f[warp], g_off_f[warp + 1], lane);
    float4 aV = agg_list(hV, g_ev, g_off_v[warp], g_off_v[warp + 1], lane);
    float fF = g_inv_fd[warp];
    float fV = g_inv_vd[warp];
    float4 b1 = __ldg((const float4*)bF + lane);
    float4 b2 = __ldg((const float4*)bV + lane);

    float4 o;
    o.x = 0.5f * (fF * aF.x + fV * aV.x + b1.x + b2.x);
    o.y = 0.5f * (fF * aF.y + fV * aV.y + b1.y + b2.y);
    o.z = 0.5f * (fF * aF.z + fV * aV.z + b1.z + b2.z);
    o.w = 0.5f * (fF * aF.w + fV * aV.w + b1.w + b2.w);
    if (RELU) {
        o.x = fmaxf(o.x, 0.f); o.y = fmaxf(o.y, 0.f);
        o.z = fmaxf(o.z, 0.f); o.w = fmaxf(o.w, 0.f);
    }
    ((float4*)outp)[(size_t)warp * 32 + lane] = o;
}

template <bool RELU>
__global__ void __launch_bounds__(256) k_agg_item(
    const __half* __restrict__ h, const float* __restrict__ b,
    float* __restrict__ outp) {
    int warp = (blockIdx.x * blockDim.x + threadIdx.x) >> 5;
    if (warp >= NI) return;
    int lane = threadIdx.x & 31;

    float4 a = agg_list(h, g_er, g_off_r[warp], g_off_r[warp + 1], lane);
    float f = g_inv_rd[warp];
    float4 bb = __ldg((const float4*)b + lane);

    float4 o;
    o.x = f * a.x + bb.x;
    o.y = f * a.y + bb.y;
    o.z = f * a.z + bb.z;
    o.w = f * a.w + bb.w;
    if (RELU) {
        o.x = fmaxf(o.x, 0.f); o.y = fmaxf(o.y, 0.f);
        o.z = fmaxf(o.z, 0.f); o.w = fmaxf(o.w, 0.f);
    }
    ((float4*)outp)[(size_t)warp * 32 + lane] = o;
}

// ---------------- host driver --------------------------------------------------

extern "C" void kernel_launch(void* const* d_in, const int* in_sizes, int n_in,
                              void* d_out, int out_size) {
    const float* x_user = (const float*)d_in[0];
    const float* x_item = (const float*)d_in[1];
    const int* f_src = (const int*)d_in[2];
    const int* f_dst = (const int*)d_in[3];
    const int* r_src = (const int*)d_in[4];
    const int* r_dst = (const int*)d_in[5];
    const int* v_src = (const int*)d_in[6];
    const int* v_dst = (const int*)d_in[7];

    const float *W1f, *W1r, *W1v, *W2f, *W2r, *W2v;
    const float *b1f, *b1r, *b1v, *b2f, *b2r, *b2v;
    if (in_sizes[9] == 128 * 128) {
        W1f = (const float*)d_in[8];  W1r = (const float*)d_in[9];  W1v = (const float*)d_in[10];
        W2f = (const float*)d_in[11]; W2r = (const float*)d_in[12]; W2v = (const float*)d_in[13];
        b1f = (const float*)d_in[14]; b1r = (const float*)d_in[15]; b1v = (const float*)d_in[16];
        b2f = (const float*)d_in[17]; b2r = (const float*)d_in[18]; b2v = (const float*)d_in[19];
    } else {
        W1f = (const float*)d_in[8];  b1f = (const float*)d_in[9];
        W1r = (const float*)d_in[10]; b1r = (const float*)d_in[11];
        W1v = (const float*)d_in[12]; b1v = (const float*)d_in[13];
        W2f = (const float*)d_in[14]; b2f = (const float*)d_in[15];
        W2r = (const float*)d_in[16]; b2r = (const float*)d_in[17];
        W2v = (const float*)d_in[18]; b2v = (const float*)d_in[19];
    }
    float* out = (float*)d_out;

    __half *hu1, *hu2, *hi, *hu1b, *hu2b, *hib;
    float *u, *it;
    cudaGetSymbolAddress((void**)&hu1, g_hu1);
    cudaGetSymbolAddress((void**)&hu2, g_hu2);
    cudaGetSymbolAddress((void**)&hi,  g_hi);
    cudaGetSymbolAddress((void**)&hu1b, g_hu1b);
    cudaGetSymbolAddress((void**)&hu2b, g_hu2b);
    cudaGetSymbolAddress((void**)&hib,  g_hib);
    cudaGetSymbolAddress((void**)&u,  g_u);
    cudaGetSymbolAddress((void**)&it, g_it);

    static cudaStream_t s1 = 0;
    static cudaEvent_t evFork = 0, evCSR = 0, evHu2 = 0, evItG = 0, evHu2b = 0, evEnd = 0;
    if (s1 == 0) {
        cudaStreamCreateWithFlags(&s1, cudaStreamNonBlocking);
        cudaEventCreateWithFlags(&evFork, cudaEventDisableTiming);
        cudaEventCreateWithFlags(&evCSR,  cudaEventDisableTiming);
        cudaEventCreateWithFlags(&evHu2,  cudaEventDisableTiming);
        cudaEventCreateWithFlags(&evItG,  cudaEventDisableTiming);
        cudaEventCreateWithFlags(&evHu2b, cudaEventDisableTiming);
        cudaEventCreateWithFlags(&evEnd,  cudaEventDisableTiming);
    }

    const int TB = 256;
    cudaFuncSetAttribute(k_gemm, cudaFuncAttributeMaxDynamicSharedMemorySize, GEMM_SMEM);

    int gNU   = (NU + TB - 1) / TB;
    int gAggU = (NU * 32 + TB - 1) / TB;
    int gAggI = (NI * 32 + TB - 1) / TB;
    int nbU = (NU + 1023) / 1024;

    dim3 gEdge3((NE + TB - 1) / TB, 3);
    dim3 gScan1(nbU, 3);
    dim3 gScan3((NU + 1 + TB - 1) / TB, 3);

    // ---- fork: CSR build on s1 (DRAM/atomic-bound) --------------------------
    cudaEventRecord(evFork, 0);
    cudaStreamWaitEvent(s1, evFork, 0);
    k_zero_hists<<<gNU, TB, 0, s1>>>();
    k_hist3<<<gEdge3, TB, 0, s1>>>(f_src, f_dst, r_src, r_dst, v_src, v_dst);
    k_inv_all<<<gNU, TB, 0, s1>>>();
    k_scan1<<<gScan1, 1024, 0, s1>>>();
    k_scan2<<<3, 1024, 0, s1>>>();
    k_scan3<<<gScan3, TB, 0, s1>>>();
    k_fill3<<<gEdge3, TB, 0, s1>>>(f_src, f_dst, r_src, r_dst, v_src, v_dst);
    cudaEventRecord(evCSR, s1);

    // ---- legacy: layer-1 GEMMs (fma-bound, overlaps CSR) ---------------------
    k_gemm<<<(NU + 63) / 64, 256, GEMM_SMEM>>>(x_user, W1r, hu2, NU);
    cudaEventRecord(evHu2, 0);
    k_gemm<<<(NU + 63) / 64, 256, GEMM_SMEM>>>(x_user, W1f, hu1, NU);
    k_gemm<<<(NI + 63) / 64, 256, GEMM_SMEM>>>(x_item, W1v, hi,  NI);

    // ---- item pipeline on s1: agg_item1 -> it@W2v ----------------------------
    cudaStreamWaitEvent(s1, evHu2, 0);
    k_agg_item<true><<<gAggI, TB, 0, s1>>>(hu2, b1r, it);
    k_gemm<<<(NI + 63) / 64, 256, GEMM_SMEM, s1>>>(it, W2v, hib, NI);
    cudaEventRecord(evItG, s1);

    // ---- user pipeline on legacy ---------------------------------------------
    cudaStreamWaitEvent(0, evCSR, 0);
    k_agg_user<true><<<gAggU, TB>>>(hu1, hi, b1f, b1v, u);
    k_gemm<<<(NU + 63) / 64, 256, GEMM_SMEM>>>(u, W2f, hu1b, NU);
    k_gemm<<<(NU + 63) / 64, 256, GEMM_SMEM>>>(u, W2r, hu2b, NU);
    cudaEventRecord(evHu2b, 0);

    // ---- final aggregations (overlapped across streams) ----------------------
    cudaStreamWaitEvent(s1, evHu2b, 0);
    k_agg_item<false><<<gAggI, TB, 0, s1>>>(hu2b, b2r, out + (size_t)NU * D);
    cudaEventRecord(evEnd, s1);

    cudaStreamWaitEvent(0, evItG, 0);
    k_agg_user<false><<<gAggU, TB>>>(hu1b, hib, b2f, b2v, out);
    cudaStreamWaitEvent(0, evEnd, 0);  // join
}